// round 2
// baseline (speedup 1.0000x reference)
#include <cuda_runtime.h>
#include <math.h>

#define NN      20000
#define EE      320000
#define ETOT    (EE + NN)     // 340000 with self-loops
#define IN_DIM  128
#define HID     256
#define HEADS   4
#define HD      64
#define OUT_DIM 128

// ------------------- scratch (device globals; no allocation) -------------------
__device__ float g_h1[(size_t)NN * HID];     // x @ W1
__device__ float g_out1[(size_t)NN * HID];   // layer1 aggregation, then BN+ELU in place
__device__ float g_h2[(size_t)NN * OUT_DIM]; // h @ W2
__device__ float g_out2[(size_t)NN * OUT_DIM];

__device__ int g_src[ETOT], g_dst[ETOT];
__device__ int g_is64;

__device__ float g_as1[NN * HEADS], g_ad1[NN * HEADS];
__device__ float g_m1[NN * HEADS], g_den1[NN * HEADS];
__device__ float g_e1[(size_t)ETOT * HEADS];

__device__ float g_as2[NN], g_ad2[NN];
__device__ float g_m2[NN], g_den2[NN];
__device__ float g_e2[ETOT];

__device__ float g_sum[HID], g_sqs[HID];

// ------------------- dtype detection + edge decode -------------------
__global__ void k_detect(const void* __restrict__ ei) {
    // If data is真 int64, every value is a node id < NN. If it is int32,
    // each int64-view packs two node ids -> value >= 2^32 unless hi word == 0.
    const unsigned long long* p = (const unsigned long long*)ei;
    int is64 = 1;
    for (int k = 0; k < 16; k++)
        if (p[k] >= (unsigned long long)NN) { is64 = 0; break; }
    g_is64 = is64;
}
__global__ void k_decode(const void* __restrict__ ei) {
    int e = blockIdx.x * blockDim.x + threadIdx.x;
    if (e >= ETOT) return;
    if (e >= EE) { g_src[e] = e - EE; g_dst[e] = e - EE; return; }
    if (g_is64) {
        const long long* p = (const long long*)ei;
        g_src[e] = (int)p[e];
        g_dst[e] = (int)p[EE + e];
    } else {
        const int* p = (const int*)ei;
        g_src[e] = p[e];
        g_dst[e] = p[EE + e];
    }
}

// ------------------- helpers -------------------
__device__ __forceinline__ void atomicMaxF(float* addr, float v) {
    if (v >= 0.f) atomicMax((int*)addr, __float_as_int(v));
    else          atomicMin((unsigned int*)addr, __float_as_uint(v));
}

// ------------------- generic 64x64 fp32 GEMM body -------------------
__device__ __forceinline__ void sgemm64(const float* __restrict__ A,
                                        const float* __restrict__ B,
                                        float* __restrict__ C,
                                        int M, int K, int Nc) {
    __shared__ float As[16][65];
    __shared__ float Bs[16][64];
    int tid = threadIdx.x;
    int m0 = blockIdx.y * 64, n0 = blockIdx.x * 64;
    int tcol = (tid & 15) * 4;
    int trow = (tid >> 4) * 4;
    float acc[4][4] = {};
    for (int k0 = 0; k0 < K; k0 += 16) {
        #pragma unroll
        for (int i = 0; i < 4; i++) {
            int lin = tid + i * 256;
            int r = lin >> 4, c = lin & 15;
            int gr = m0 + r;
            As[c][r] = (gr < M) ? A[(size_t)gr * K + k0 + c] : 0.f;
        }
        #pragma unroll
        for (int i = 0; i < 4; i++) {
            int lin = tid + i * 256;
            int r = lin >> 6, c = lin & 63;
            Bs[r][c] = B[(size_t)(k0 + r) * Nc + n0 + c];
        }
        __syncthreads();
        #pragma unroll
        for (int k = 0; k < 16; k++) {
            float a[4], b[4];
            #pragma unroll
            for (int i = 0; i < 4; i++) { a[i] = As[k][trow + i]; b[i] = Bs[k][tcol + i]; }
            #pragma unroll
            for (int i = 0; i < 4; i++)
                #pragma unroll
                for (int j = 0; j < 4; j++) acc[i][j] += a[i] * b[j];
        }
        __syncthreads();
    }
    #pragma unroll
    for (int i = 0; i < 4; i++) {
        int gr = m0 + trow + i;
        if (gr < M) {
            #pragma unroll
            for (int j = 0; j < 4; j++)
                C[(size_t)gr * Nc + n0 + tcol + j] = acc[i][j];
        }
    }
}

__global__ void k_gemm1(const float* __restrict__ x, const float* __restrict__ W1) {
    sgemm64(x, W1, g_h1, NN, IN_DIM, HID);
}
__global__ void k_gemm2(const float* __restrict__ W2) {
    sgemm64(g_out1, W2, g_h2, NN, HID, OUT_DIM);
}

// ------------------- inits -------------------
__global__ void k_init1() {
    int i = blockIdx.x * blockDim.x + threadIdx.x;
    if (i < NN * HID) g_out1[i] = 0.f;
    if (i < NN * HEADS) { g_m1[i] = -INFINITY; g_den1[i] = 0.f; }
    if (i < HID) { g_sum[i] = 0.f; g_sqs[i] = 0.f; }
}
__global__ void k_init2() {
    int i = blockIdx.x * blockDim.x + threadIdx.x;
    if (i < NN * OUT_DIM) g_out2[i] = 0.f;
    if (i < NN) { g_m2[i] = -INFINITY; g_den2[i] = 0.f; }
    if (i < HID) { g_sum[i] = 0.f; g_sqs[i] = 0.f; }
}

// ------------------- attention coefficients -------------------
__global__ void k_alpha1(const float* __restrict__ asrc, const float* __restrict__ adst) {
    int warp = (blockIdx.x * blockDim.x + threadIdx.x) >> 5;
    int lane = threadIdx.x & 31;
    if (warp >= NN) return;
    const float* hrow = g_h1 + (size_t)warp * HID;
    #pragma unroll
    for (int h = 0; h < HEADS; h++) {
        float x0 = hrow[h * 64 + lane], x1 = hrow[h * 64 + 32 + lane];
        float vs = x0 * asrc[h * 64 + lane] + x1 * asrc[h * 64 + 32 + lane];
        float vd = x0 * adst[h * 64 + lane] + x1 * adst[h * 64 + 32 + lane];
        #pragma unroll
        for (int o = 16; o; o >>= 1) {
            vs += __shfl_down_sync(0xffffffffu, vs, o);
            vd += __shfl_down_sync(0xffffffffu, vd, o);
        }
        if (lane == 0) { g_as1[warp * HEADS + h] = vs; g_ad1[warp * HEADS + h] = vd; }
    }
}
__global__ void k_alpha2(const float* __restrict__ asrc, const float* __restrict__ adst) {
    int warp = (blockIdx.x * blockDim.x + threadIdx.x) >> 5;
    int lane = threadIdx.x & 31;
    if (warp >= NN) return;
    const float* hrow = g_h2 + (size_t)warp * OUT_DIM;
    float vs = 0.f, vd = 0.f;
    #pragma unroll
    for (int j = 0; j < 4; j++) {
        float x0 = hrow[lane + 32 * j];
        vs += x0 * asrc[lane + 32 * j];
        vd += x0 * adst[lane + 32 * j];
    }
    #pragma unroll
    for (int o = 16; o; o >>= 1) {
        vs += __shfl_down_sync(0xffffffffu, vs, o);
        vd += __shfl_down_sync(0xffffffffu, vd, o);
    }
    if (lane == 0) { g_as2[warp] = vs; g_ad2[warp] = vd; }
}

// ------------------- edge softmax passes, layer 1 (4 heads) -------------------
__global__ void k_emax1() {
    int i = blockIdx.x * blockDim.x + threadIdx.x;
    if (i >= ETOT * HEADS) return;
    int e = i >> 2, h = i & 3;
    int s = g_src[e], d = g_dst[e];
    float v = g_as1[s * HEADS + h] + g_ad1[d * HEADS + h];
    v = v > 0.f ? v : 0.2f * v;
    g_e1[i] = v;
    atomicMaxF(&g_m1[d * HEADS + h], v);
}
__global__ void k_esum1() {
    int i = blockIdx.x * blockDim.x + threadIdx.x;
    if (i >= ETOT * HEADS) return;
    int e = i >> 2, h = i & 3;
    int d = g_dst[e];
    float ex = expf(g_e1[i] - g_m1[d * HEADS + h]);
    g_e1[i] = ex;
    atomicAdd(&g_den1[d * HEADS + h], ex);
}
__global__ void k_scatter1() {
    int i = blockIdx.x * blockDim.x + threadIdx.x;
    if (i >= ETOT * 64) return;      // 64 float4 chunks of 256 channels
    int e = i >> 6, q = i & 63;
    int h = q >> 4;
    int s = g_src[e], d = g_dst[e];
    float coef = g_e1[e * HEADS + h] / (g_den1[d * HEADS + h] + 1e-16f);
    const float4 hv = *(const float4*)(g_h1 + (size_t)s * HID + q * 4);
    float* o = g_out1 + (size_t)d * HID + q * 4;
    atomicAdd(o + 0, hv.x * coef);
    atomicAdd(o + 1, hv.y * coef);
    atomicAdd(o + 2, hv.z * coef);
    atomicAdd(o + 3, hv.w * coef);
}

// ------------------- edge softmax passes, layer 2 (1 head) -------------------
__global__ void k_emax2() {
    int e = blockIdx.x * blockDim.x + threadIdx.x;
    if (e >= ETOT) return;
    int s = g_src[e], d = g_dst[e];
    float v = g_as2[s] + g_ad2[d];
    v = v > 0.f ? v : 0.2f * v;
    g_e2[e] = v;
    atomicMaxF(&g_m2[d], v);
}
__global__ void k_esum2() {
    int e = blockIdx.x * blockDim.x + threadIdx.x;
    if (e >= ETOT) return;
    int d = g_dst[e];
    float ex = expf(g_e2[e] - g_m2[d]);
    g_e2[e] = ex;
    atomicAdd(&g_den2[d], ex);
}
__global__ void k_scatter2() {
    int i = blockIdx.x * blockDim.x + threadIdx.x;
    if (i >= ETOT * 32) return;      // 32 float4 chunks of 128 channels
    int e = i >> 5, q = i & 31;
    int s = g_src[e], d = g_dst[e];
    float coef = g_e2[e] / (g_den2[d] + 1e-16f);
    const float4 hv = *(const float4*)(g_h2 + (size_t)s * OUT_DIM + q * 4);
    float* o = g_out2 + (size_t)d * OUT_DIM + q * 4;
    atomicAdd(o + 0, hv.x * coef);
    atomicAdd(o + 1, hv.y * coef);
    atomicAdd(o + 2, hv.z * coef);
    atomicAdd(o + 3, hv.w * coef);
}

// ------------------- batchnorm -------------------
__global__ void k_stats1() {
    int c = threadIdx.x;                 // 256 threads
    int r0 = blockIdx.x * 256;
    int rend = r0 + 256; if (rend > NN) rend = NN;
    float s = 0.f, s2 = 0.f;
    for (int r = r0; r < rend; r++) {
        float v = g_out1[(size_t)r * HID + c];
        s += v; s2 += v * v;
    }
    atomicAdd(&g_sum[c], s); atomicAdd(&g_sqs[c], s2);
}
__global__ void k_apply1(const float* __restrict__ gamma, const float* __restrict__ beta) {
    int i = blockIdx.x * blockDim.x + threadIdx.x;
    if (i >= NN * HID) return;
    int c = i & (HID - 1);
    float mean = g_sum[c] * (1.f / NN);
    float var = g_sqs[c] * (1.f / NN) - mean * mean;
    float v = (g_out1[i] - mean) * rsqrtf(var + 1e-5f) * gamma[c] + beta[c];
    g_out1[i] = v > 0.f ? v : expm1f(v);   // ELU
}
__global__ void k_stats2() {
    int c = threadIdx.x;                 // 128 threads
    int r0 = blockIdx.x * 256;
    int rend = r0 + 256; if (rend > NN) rend = NN;
    float s = 0.f, s2 = 0.f;
    for (int r = r0; r < rend; r++) {
        float v = g_out2[(size_t)r * OUT_DIM + c];
        s += v; s2 += v * v;
    }
    atomicAdd(&g_sum[c], s); atomicAdd(&g_sqs[c], s2);
}
__global__ void k_apply2(const float* __restrict__ gamma, const float* __restrict__ beta,
                         float* __restrict__ out) {
    int i = blockIdx.x * blockDim.x + threadIdx.x;
    if (i >= NN * OUT_DIM) return;
    int c = i & (OUT_DIM - 1);
    float mean = g_sum[c] * (1.f / NN);
    float var = g_sqs[c] * (1.f / NN) - mean * mean;
    out[i] = (g_out2[i] - mean) * rsqrtf(var + 1e-5f) * gamma[c] + beta[c];
}

// ------------------- launch -------------------
extern "C" void kernel_launch(void* const* d_in, const int* in_sizes, int n_in,
                              void* d_out, int out_size) {
    const float* x     = (const float*)d_in[0];
    const void*  ei    = d_in[1];                    // int32 or int64, detected on device
    const float* W1    = (const float*)d_in[2];
    const float* asrc1 = (const float*)d_in[3];
    const float* adst1 = (const float*)d_in[4];
    // d_in[5] = bias1 (cancels under BN)
    const float* g1    = (const float*)d_in[6];
    const float* b1    = (const float*)d_in[7];
    const float* W2    = (const float*)d_in[8];
    const float* asrc2 = (const float*)d_in[9];
    const float* adst2 = (const float*)d_in[10];
    // d_in[11] = bias2 (cancels under BN)
    const float* g2    = (const float*)d_in[12];
    const float* b2    = (const float*)d_in[13];
    float* out = (float*)d_out;

    const int T = 256;

    // ---- edge decode ----
    k_detect<<<1, 1>>>(ei);
    k_decode<<<(ETOT + T - 1) / T, T>>>(ei);

    // ---- layer 1 ----
    k_init1<<<(NN * HID + T - 1) / T, T>>>();
    k_gemm1<<<dim3(HID / 64, (NN + 63) / 64), 256>>>(x, W1);
    k_alpha1<<<(NN * 32 + T - 1) / T, T>>>(asrc1, adst1);
    k_emax1<<<(ETOT * HEADS + T - 1) / T, T>>>();
    k_esum1<<<(ETOT * HEADS + T - 1) / T, T>>>();
    k_scatter1<<<(ETOT * 64 + T - 1) / T, T>>>();
    k_stats1<<<(NN + 255) / 256, 256>>>();
    k_apply1<<<(NN * HID + T - 1) / T, T>>>(g1, b1);

    // ---- layer 2 ----
    k_init2<<<(NN * OUT_DIM + T - 1) / T, T>>>();
    k_gemm2<<<dim3(OUT_DIM / 64, (NN + 63) / 64), 256>>>(W2);
    k_alpha2<<<(NN * 32 + T - 1) / T, T>>>(asrc2, adst2);
    k_emax2<<<(ETOT + T - 1) / T, T>>>();
    k_esum2<<<(ETOT + T - 1) / T, T>>>();
    k_scatter2<<<(ETOT * 32 + T - 1) / T, T>>>();
    k_stats2<<<(NN + 255) / 256, 128>>>();
    k_apply2<<<(NN * OUT_DIM + T - 1) / T, T>>>(g2, b2, out);
}

// round 3
// speedup vs baseline: 1.9007x; 1.9007x over previous
#include <cuda_runtime.h>
#include <math.h>

#define NN      20000
#define EE      320000
#define ETOT    (EE + NN)     // +self-loops
#define IN_DIM  128
#define HID     256
#define HEADS   4
#define OUT_DIM 128

// ------------------- scratch (device globals) -------------------
__device__ float g_h1[(size_t)NN * HID];
__device__ float g_out1[(size_t)NN * HID];
__device__ float g_h2[(size_t)NN * OUT_DIM];
__device__ float g_out2[(size_t)NN * OUT_DIM];

__device__ int g_srcA[ETOT], g_dstA[ETOT];
__device__ int g_cnt[NN];
__device__ int g_off[NN + 1];
__device__ int g_pos[NN];
__device__ int g_csr[ETOT];         // src ids sorted by dst
__device__ int g_is64;

__device__ float g_as1[NN * HEADS], g_ad1[NN * HEADS];
__device__ float g_as2[NN], g_ad2[NN];
__device__ float g_sum[HID], g_sqs[HID];

// ------------------- dtype detection + edge decode -------------------
__global__ void k_detect(const void* __restrict__ ei) {
    const unsigned long long* p = (const unsigned long long*)ei;
    int is64 = 1;
    for (int k = 0; k < 16; k++)
        if (p[k] >= (unsigned long long)NN) { is64 = 0; break; }
    g_is64 = is64;
}
__global__ void k_decode(const void* __restrict__ ei) {
    int e = blockIdx.x * blockDim.x + threadIdx.x;
    if (e >= ETOT) return;
    if (e < NN) g_cnt[e] = 0;
    if (e >= EE) { g_srcA[e] = e - EE; g_dstA[e] = e - EE; return; }
    if (g_is64) {
        const long long* p = (const long long*)ei;
        g_srcA[e] = (int)p[e];
        g_dstA[e] = (int)p[EE + e];
    } else {
        const int* p = (const int*)ei;
        g_srcA[e] = p[e];
        g_dstA[e] = p[EE + e];
    }
}
__global__ void k_count() {
    int e = blockIdx.x * blockDim.x + threadIdx.x;
    if (e >= ETOT) return;
    atomicAdd(&g_cnt[g_dstA[e]], 1);
}
__global__ void k_scan() {        // single block, 256 threads
    __shared__ int part[256];
    int tid = threadIdx.x;
    const int CH = (NN + 255) / 256;
    int base = tid * CH;
    int s = 0;
    for (int i = 0; i < CH; i++) { int idx = base + i; if (idx < NN) s += g_cnt[idx]; }
    part[tid] = s; __syncthreads();
    for (int o = 1; o < 256; o <<= 1) {
        int v = (tid >= o) ? part[tid - o] : 0;
        __syncthreads();
        part[tid] += v;
        __syncthreads();
    }
    int run = tid ? part[tid - 1] : 0;
    for (int i = 0; i < CH; i++) {
        int idx = base + i;
        if (idx < NN) { g_off[idx] = run; g_pos[idx] = run; run += g_cnt[idx]; }
    }
    if (tid == 255) g_off[NN] = run;
}
__global__ void k_fill() {
    int e = blockIdx.x * blockDim.x + threadIdx.x;
    if (e >= ETOT) return;
    int p = atomicAdd(&g_pos[g_dstA[e]], 1);
    g_csr[p] = g_srcA[e];
}

// ------------------- generic 64x64 fp32 GEMM -------------------
__device__ __forceinline__ void sgemm64(const float* __restrict__ A,
                                        const float* __restrict__ B,
                                        float* __restrict__ C,
                                        int M, int K, int Nc) {
    __shared__ float As[16][65];
    __shared__ float Bs[16][64];
    int tid = threadIdx.x;
    int m0 = blockIdx.y * 64, n0 = blockIdx.x * 64;
    int tcol = (tid & 15) * 4;
    int trow = (tid >> 4) * 4;
    float acc[4][4] = {};
    for (int k0 = 0; k0 < K; k0 += 16) {
        #pragma unroll
        for (int i = 0; i < 4; i++) {
            int lin = tid + i * 256;
            int r = lin >> 4, c = lin & 15;
            int gr = m0 + r;
            As[c][r] = (gr < M) ? A[(size_t)gr * K + k0 + c] : 0.f;
        }
        #pragma unroll
        for (int i = 0; i < 4; i++) {
            int lin = tid + i * 256;
            int r = lin >> 6, c = lin & 63;
            Bs[r][c] = B[(size_t)(k0 + r) * Nc + n0 + c];
        }
        __syncthreads();
        #pragma unroll
        for (int k = 0; k < 16; k++) {
            float a[4], b[4];
            #pragma unroll
            for (int i = 0; i < 4; i++) { a[i] = As[k][trow + i]; b[i] = Bs[k][tcol + i]; }
            #pragma unroll
            for (int i = 0; i < 4; i++)
                #pragma unroll
                for (int j = 0; j < 4; j++) acc[i][j] += a[i] * b[j];
        }
        __syncthreads();
    }
    #pragma unroll
    for (int i = 0; i < 4; i++) {
        int gr = m0 + trow + i;
        if (gr < M) {
            #pragma unroll
            for (int j = 0; j < 4; j++)
                C[(size_t)gr * Nc + n0 + tcol + j] = acc[i][j];
        }
    }
}
__global__ void k_gemm1(const float* __restrict__ x, const float* __restrict__ W1) {
    sgemm64(x, W1, g_h1, NN, IN_DIM, HID);
}
__global__ void k_gemm2(const float* __restrict__ W2) {
    sgemm64(g_out1, W2, g_h2, NN, HID, OUT_DIM);
}

// ------------------- attention logits -------------------
__global__ void k_alpha1(const float* __restrict__ asrc, const float* __restrict__ adst) {
    int warp = (blockIdx.x * blockDim.x + threadIdx.x) >> 5;
    int lane = threadIdx.x & 31;
    if (warp >= NN) return;
    const float* hrow = g_h1 + (size_t)warp * HID;
    #pragma unroll
    for (int h = 0; h < HEADS; h++) {
        float x0 = hrow[h * 64 + lane], x1 = hrow[h * 64 + 32 + lane];
        float vs = x0 * asrc[h * 64 + lane] + x1 * asrc[h * 64 + 32 + lane];
        float vd = x0 * adst[h * 64 + lane] + x1 * adst[h * 64 + 32 + lane];
        #pragma unroll
        for (int o = 16; o; o >>= 1) {
            vs += __shfl_down_sync(0xffffffffu, vs, o);
            vd += __shfl_down_sync(0xffffffffu, vd, o);
        }
        if (lane == 0) { g_as1[warp * HEADS + h] = vs; g_ad1[warp * HEADS + h] = vd; }
    }
}
__global__ void k_alpha2(const float* __restrict__ asrc, const float* __restrict__ adst) {
    int warp = (blockIdx.x * blockDim.x + threadIdx.x) >> 5;
    int lane = threadIdx.x & 31;
    if (warp >= NN) return;
    const float* hrow = g_h2 + (size_t)warp * OUT_DIM;
    float vs = 0.f, vd = 0.f;
    #pragma unroll
    for (int j = 0; j < 4; j++) {
        float x0 = hrow[lane + 32 * j];
        vs += x0 * asrc[lane + 32 * j];
        vd += x0 * adst[lane + 32 * j];
    }
    #pragma unroll
    for (int o = 16; o; o >>= 1) {
        vs += __shfl_down_sync(0xffffffffu, vs, o);
        vd += __shfl_down_sync(0xffffffffu, vd, o);
    }
    if (lane == 0) { g_as2[warp] = vs; g_ad2[warp] = vd; }
}

// ------------------- fused softmax + gather, layer 1 -------------------
__device__ __forceinline__ float lrelu(float v) { return v > 0.f ? v : 0.2f * v; }

__global__ void k_agg1() {
    int gw = (blockIdx.x * blockDim.x + threadIdx.x) >> 5;
    int lane = threadIdx.x & 31;
    if (gw >= NN) return;
    int beg = g_off[gw], end = g_off[gw + 1];
    float4 adv = *(const float4*)(g_ad1 + gw * 4);

    // pass 1a: per-head max (lane-partitioned over edges)
    float4 mx = make_float4(-INFINITY, -INFINITY, -INFINITY, -INFINITY);
    for (int i = beg + lane; i < end; i += 32) {
        int s = g_csr[i];
        float4 a = *(const float4*)(g_as1 + s * 4);
        mx.x = fmaxf(mx.x, lrelu(a.x + adv.x));
        mx.y = fmaxf(mx.y, lrelu(a.y + adv.y));
        mx.z = fmaxf(mx.z, lrelu(a.z + adv.z));
        mx.w = fmaxf(mx.w, lrelu(a.w + adv.w));
    }
    #pragma unroll
    for (int o = 16; o; o >>= 1) {
        mx.x = fmaxf(mx.x, __shfl_xor_sync(0xffffffffu, mx.x, o));
        mx.y = fmaxf(mx.y, __shfl_xor_sync(0xffffffffu, mx.y, o));
        mx.z = fmaxf(mx.z, __shfl_xor_sync(0xffffffffu, mx.z, o));
        mx.w = fmaxf(mx.w, __shfl_xor_sync(0xffffffffu, mx.w, o));
    }
    // pass 1b: exp-sum
    float4 den = make_float4(0.f, 0.f, 0.f, 0.f);
    for (int i = beg + lane; i < end; i += 32) {
        int s = g_csr[i];
        float4 a = *(const float4*)(g_as1 + s * 4);
        den.x += expf(lrelu(a.x + adv.x) - mx.x);
        den.y += expf(lrelu(a.y + adv.y) - mx.y);
        den.z += expf(lrelu(a.z + adv.z) - mx.z);
        den.w += expf(lrelu(a.w + adv.w) - mx.w);
    }
    #pragma unroll
    for (int o = 16; o; o >>= 1) {
        den.x += __shfl_xor_sync(0xffffffffu, den.x, o);
        den.y += __shfl_xor_sync(0xffffffffu, den.y, o);
        den.z += __shfl_xor_sync(0xffffffffu, den.z, o);
        den.w += __shfl_xor_sync(0xffffffffu, den.w, o);
    }

    // per-lane head selection: lane handles channels [lane*8, lane*8+8) -> head = lane/8
    int hsel = lane >> 3;
    float ad_l  = hsel == 0 ? adv.x : hsel == 1 ? adv.y : hsel == 2 ? adv.z : adv.w;
    float m_l   = hsel == 0 ? mx.x  : hsel == 1 ? mx.y  : hsel == 2 ? mx.z  : mx.w;
    float den_l = hsel == 0 ? den.x : hsel == 1 ? den.y : hsel == 2 ? den.z : den.w;
    float inv_l = 1.f / (den_l + 1e-16f);

    // pass 2: gather & accumulate (whole warp per edge)
    float4 acc0 = make_float4(0.f, 0.f, 0.f, 0.f);
    float4 acc1 = make_float4(0.f, 0.f, 0.f, 0.f);
    const float4* __restrict__ h1v = (const float4*)g_h1;
    for (int i = beg; i < end; i++) {
        int s = g_csr[i];
        float a = g_as1[(s << 2) + hsel];
        float c = expf(lrelu(a + ad_l) - m_l) * inv_l;
        float4 v0 = h1v[(size_t)s * 64 + lane * 2];
        float4 v1 = h1v[(size_t)s * 64 + lane * 2 + 1];
        acc0.x += v0.x * c; acc0.y += v0.y * c; acc0.z += v0.z * c; acc0.w += v0.w * c;
        acc1.x += v1.x * c; acc1.y += v1.y * c; acc1.z += v1.z * c; acc1.w += v1.w * c;
    }
    float4* ov = (float4*)(g_out1 + (size_t)gw * HID);
    ov[lane * 2] = acc0;
    ov[lane * 2 + 1] = acc1;
}

// ------------------- fused softmax + gather, layer 2 -------------------
__global__ void k_agg2() {
    int gw = (blockIdx.x * blockDim.x + threadIdx.x) >> 5;
    int lane = threadIdx.x & 31;
    if (gw >= NN) return;
    int beg = g_off[gw], end = g_off[gw + 1];
    float ad = g_ad2[gw];

    float mx = -INFINITY;
    for (int i = beg + lane; i < end; i += 32)
        mx = fmaxf(mx, lrelu(g_as2[g_csr[i]] + ad));
    #pragma unroll
    for (int o = 16; o; o >>= 1) mx = fmaxf(mx, __shfl_xor_sync(0xffffffffu, mx, o));

    float den = 0.f;
    for (int i = beg + lane; i < end; i += 32)
        den += expf(lrelu(g_as2[g_csr[i]] + ad) - mx);
    #pragma unroll
    for (int o = 16; o; o >>= 1) den += __shfl_xor_sync(0xffffffffu, den, o);
    float inv = 1.f / (den + 1e-16f);

    float4 acc = make_float4(0.f, 0.f, 0.f, 0.f);
    const float4* __restrict__ h2v = (const float4*)g_h2;
    for (int i = beg; i < end; i++) {
        int s = g_csr[i];
        float c = expf(lrelu(g_as2[s] + ad) - mx) * inv;
        float4 v = h2v[(size_t)s * 32 + lane];
        acc.x += v.x * c; acc.y += v.y * c; acc.z += v.z * c; acc.w += v.w * c;
    }
    ((float4*)(g_out2 + (size_t)gw * OUT_DIM))[lane] = acc;
}

// ------------------- batchnorm -------------------
__global__ void k_zero_bn() {
    int i = threadIdx.x;
    if (i < HID) { g_sum[i] = 0.f; g_sqs[i] = 0.f; }
}
__global__ void k_stats1() {
    int c = threadIdx.x;
    int r0 = blockIdx.x * 256;
    int rend = r0 + 256; if (rend > NN) rend = NN;
    float s = 0.f, s2 = 0.f;
    for (int r = r0; r < rend; r++) {
        float v = g_out1[(size_t)r * HID + c];
        s += v; s2 += v * v;
    }
    atomicAdd(&g_sum[c], s); atomicAdd(&g_sqs[c], s2);
}
__global__ void k_apply1(const float* __restrict__ gamma, const float* __restrict__ beta) {
    int i = blockIdx.x * blockDim.x + threadIdx.x;
    if (i >= NN * HID) return;
    int c = i & (HID - 1);
    float mean = g_sum[c] * (1.f / NN);
    float var = g_sqs[c] * (1.f / NN) - mean * mean;
    float v = (g_out1[i] - mean) * rsqrtf(var + 1e-5f) * gamma[c] + beta[c];
    g_out1[i] = v > 0.f ? v : expm1f(v);   // ELU
}
__global__ void k_stats2() {
    int c = threadIdx.x;
    int r0 = blockIdx.x * 256;
    int rend = r0 + 256; if (rend > NN) rend = NN;
    float s = 0.f, s2 = 0.f;
    for (int r = r0; r < rend; r++) {
        float v = g_out2[(size_t)r * OUT_DIM + c];
        s += v; s2 += v * v;
    }
    atomicAdd(&g_sum[c], s); atomicAdd(&g_sqs[c], s2);
}
__global__ void k_apply2(const float* __restrict__ gamma, const float* __restrict__ beta,
                         float* __restrict__ out) {
    int i = blockIdx.x * blockDim.x + threadIdx.x;
    if (i >= NN * OUT_DIM) return;
    int c = i & (OUT_DIM - 1);
    float mean = g_sum[c] * (1.f / NN);
    float var = g_sqs[c] * (1.f / NN) - mean * mean;
    out[i] = (g_out2[i] - mean) * rsqrtf(var + 1e-5f) * gamma[c] + beta[c];
}

// ------------------- launch -------------------
extern "C" void kernel_launch(void* const* d_in, const int* in_sizes, int n_in,
                              void* d_out, int out_size) {
    const float* x     = (const float*)d_in[0];
    const void*  ei    = d_in[1];
    const float* W1    = (const float*)d_in[2];
    const float* asrc1 = (const float*)d_in[3];
    const float* adst1 = (const float*)d_in[4];
    const float* g1    = (const float*)d_in[6];
    const float* b1    = (const float*)d_in[7];
    const float* W2    = (const float*)d_in[8];
    const float* asrc2 = (const float*)d_in[9];
    const float* adst2 = (const float*)d_in[10];
    const float* g2    = (const float*)d_in[12];
    const float* b2    = (const float*)d_in[13];
    float* out = (float*)d_out;

    const int T = 256;
    const int EB = (ETOT + T - 1) / T;

    // CSR build
    k_detect<<<1, 1>>>(ei);
    k_decode<<<EB, T>>>(ei);
    k_count<<<EB, T>>>();
    k_scan<<<1, 256>>>();
    k_fill<<<EB, T>>>();

    // layer 1
    k_gemm1<<<dim3(HID / 64, (NN + 63) / 64), 256>>>(x, W1);
    k_alpha1<<<(NN * 32 + T - 1) / T, T>>>(asrc1, adst1);
    k_agg1<<<(NN * 32 + T - 1) / T, T>>>();
    k_zero_bn<<<1, 256>>>();
    k_stats1<<<(NN + 255) / 256, 256>>>();
    k_apply1<<<(NN * HID + T - 1) / T, T>>>(g1, b1);

    // layer 2
    k_gemm2<<<dim3(OUT_DIM / 64, (NN + 63) / 64), 256>>>(W2);
    k_alpha2<<<(NN * 32 + T - 1) / T, T>>>(asrc2, adst2);
    k_agg2<<<(NN * 32 + T - 1) / T, T>>>();
    k_zero_bn<<<1, 256>>>();
    k_stats2<<<(NN + 255) / 256, 128>>>();
    k_apply2<<<(NN * OUT_DIM + T - 1) / T, T>>>(g2, b2, out);
}

// round 6
// speedup vs baseline: 2.0345x; 1.0704x over previous
#include <cuda_runtime.h>
#include <math.h>

#define NN      20000
#define EE      320000
#define ETOT    (EE + NN)     // +self-loops
#define IN_DIM  128
#define HID     256
#define HEADS   4
#define OUT_DIM 128

// ------------------- scratch (device globals) -------------------
__device__ float g_h1[(size_t)NN * HID];
__device__ float g_out1[(size_t)NN * HID];
__device__ float g_h2[(size_t)NN * OUT_DIM];
__device__ float g_out2[(size_t)NN * OUT_DIM];

__device__ int g_srcA[ETOT], g_dstA[ETOT];
__device__ int g_cnt[NN];
__device__ int g_off[NN + 1];
__device__ int g_pos[NN];
__device__ int g_csr[ETOT];         // src ids sorted by dst
__device__ int g_is64;

__device__ float g_as1[NN * HEADS], g_ad1[NN * HEADS];
__device__ float g_as2[NN], g_ad2[NN];
__device__ float g_sum[HID], g_sqs[HID];

// ------------------- dtype detection + edge decode -------------------
__global__ void k_detect(const void* __restrict__ ei) {
    const unsigned long long* p = (const unsigned long long*)ei;
    int is64 = 1;
    for (int k = 0; k < 16; k++)
        if (p[k] >= (unsigned long long)NN) { is64 = 0; break; }
    g_is64 = is64;
}
__global__ void k_decode(const void* __restrict__ ei) {
    int e = blockIdx.x * blockDim.x + threadIdx.x;
    if (e >= ETOT) return;
    if (e < NN) g_cnt[e] = 0;
    if (e >= EE) { g_srcA[e] = e - EE; g_dstA[e] = e - EE; return; }
    if (g_is64) {
        const long long* p = (const long long*)ei;
        g_srcA[e] = (int)p[e];
        g_dstA[e] = (int)p[EE + e];
    } else {
        const int* p = (const int*)ei;
        g_srcA[e] = p[e];
        g_dstA[e] = p[EE + e];
    }
}
__global__ void k_count() {
    int e = blockIdx.x * blockDim.x + threadIdx.x;
    if (e >= ETOT) return;
    atomicAdd(&g_cnt[g_dstA[e]], 1);
}
// single block, 1024 threads, 20 elems per thread, warp-shuffle scan
__global__ void k_scan() {
    __shared__ int warpsum[32];
    int tid = threadIdx.x;
    int lane = tid & 31, wid = tid >> 5;
    const int CH = 20;                       // 1024*20 = 20480 >= NN
    int base = tid * CH;
    int s = 0;
    #pragma unroll
    for (int i = 0; i < CH; i++) {
        int idx = base + i;
        if (idx < NN) s += g_cnt[idx];
    }
    // inclusive warp scan
    int ps = s;
    #pragma unroll
    for (int o = 1; o < 32; o <<= 1) {
        int t = __shfl_up_sync(0xffffffffu, ps, o);
        if (lane >= o) ps += t;
    }
    if (lane == 31) warpsum[wid] = ps;
    __syncthreads();
    if (wid == 0) {
        int w = warpsum[lane];
        #pragma unroll
        for (int o = 1; o < 32; o <<= 1) {
            int t = __shfl_up_sync(0xffffffffu, w, o);
            if (lane >= o) w += t;
        }
        warpsum[lane] = w;
    }
    __syncthreads();
    int run = ps - s + (wid ? warpsum[wid - 1] : 0);  // exclusive prefix
    #pragma unroll
    for (int i = 0; i < CH; i++) {
        int idx = base + i;
        if (idx < NN) { g_off[idx] = run; g_pos[idx] = run; run += g_cnt[idx]; }
    }
    if (tid == 0) g_off[NN] = warpsum[31];
}
__global__ void k_fill() {
    int e = blockIdx.x * blockDim.x + threadIdx.x;
    if (e >= ETOT) return;
    int p = atomicAdd(&g_pos[g_dstA[e]], 1);
    g_csr[p] = g_srcA[e];
}

// ------------------- 128x64-tile fp32 GEMM, float4 LDS -------------------
__device__ __forceinline__ void sgemm128x64(const float* __restrict__ A,
                                            const float* __restrict__ B,
                                            float* __restrict__ C,
                                            int M, int K, int Nc) {
    __shared__ float As[16][132];   // [k][row], pad to 132 (16B-aligned rows, 2-way store conflict max)
    __shared__ float Bs[16][64];    // [k][col]
    int tid = threadIdx.x;
    int m0 = blockIdx.y * 128, n0 = blockIdx.x * 64;
    int trow = (tid >> 4) * 8;
    int tcol = (tid & 15) * 4;
    float acc[8][4] = {};
    for (int k0 = 0; k0 < K; k0 += 16) {
        #pragma unroll
        for (int i = 0; i < 8; i++) {
            int lin = tid + i * 256;
            int r = lin >> 4, c = lin & 15;
            int gr = m0 + r;
            As[c][r] = (gr < M) ? A[(size_t)gr * K + k0 + c] : 0.f;
        }
        #pragma unroll
        for (int i = 0; i < 4; i++) {
            int lin = tid + i * 256;
            int r = lin >> 6, c = lin & 63;
            Bs[r][c] = B[(size_t)(k0 + r) * Nc + n0 + c];
        }
        __syncthreads();
        #pragma unroll
        for (int k = 0; k < 16; k++) {
            float4 a0 = *(const float4*)&As[k][trow];
            float4 a1 = *(const float4*)&As[k][trow + 4];
            float4 bv = *(const float4*)&Bs[k][tcol];
            float a[8] = {a0.x, a0.y, a0.z, a0.w, a1.x, a1.y, a1.z, a1.w};
            float b[4] = {bv.x, bv.y, bv.z, bv.w};
            #pragma unroll
            for (int i = 0; i < 8; i++)
                #pragma unroll
                for (int j = 0; j < 4; j++) acc[i][j] += a[i] * b[j];
        }
        __syncthreads();
    }
    #pragma unroll
    for (int i = 0; i < 8; i++) {
        int gr = m0 + trow + i;
        if (gr < M) {
            float4 v = make_float4(acc[i][0], acc[i][1], acc[i][2], acc[i][3]);
            *(float4*)&C[(size_t)gr * Nc + n0 + tcol] = v;
        }
    }
}
__global__ void k_gemm1(const float* __restrict__ x, const float* __restrict__ W1) {
    sgemm128x64(x, W1, g_h1, NN, IN_DIM, HID);
}
__global__ void k_gemm2(const float* __restrict__ W2) {
    sgemm128x64(g_out1, W2, g_h2, NN, HID, OUT_DIM);
}

// ------------------- attention logits -------------------
__global__ void k_alpha1(const float* __restrict__ asrc, const float* __restrict__ adst) {
    int warp = (blockIdx.x * blockDim.x + threadIdx.x) >> 5;
    int lane = threadIdx.x & 31;
    if (warp >= NN) return;
    const float* hrow = g_h1 + (size_t)warp * HID;
    #pragma unroll
    for (int h = 0; h < HEADS; h++) {
        float x0 = hrow[h * 64 + lane], x1 = hrow[h * 64 + 32 + lane];
        float vs = x0 * asrc[h * 64 + lane] + x1 * asrc[h * 64 + 32 + lane];
        float vd = x0 * adst[h * 64 + lane] + x1 * adst[h * 64 + 32 + lane];
        #pragma unroll
        for (int o = 16; o; o >>= 1) {
            vs += __shfl_down_sync(0xffffffffu, vs, o);
            vd += __shfl_down_sync(0xffffffffu, vd, o);
        }
        if (lane == 0) { g_as1[warp * HEADS + h] = vs; g_ad1[warp * HEADS + h] = vd; }
    }
}
__global__ void k_alpha2(const float* __restrict__ asrc, const float* __restrict__ adst) {
    int warp = (blockIdx.x * blockDim.x + threadIdx.x) >> 5;
    int lane = threadIdx.x & 31;
    if (warp >= NN) return;
    const float* hrow = g_h2 + (size_t)warp * OUT_DIM;
    float vs = 0.f, vd = 0.f;
    #pragma unroll
    for (int j = 0; j < 4; j++) {
        float x0 = hrow[lane + 32 * j];
        vs += x0 * asrc[lane + 32 * j];
        vd += x0 * adst[lane + 32 * j];
    }
    #pragma unroll
    for (int o = 16; o; o >>= 1) {
        vs += __shfl_down_sync(0xffffffffu, vs, o);
        vd += __shfl_down_sync(0xffffffffu, vd, o);
    }
    if (lane == 0) { g_as2[warp] = vs; g_ad2[warp] = vd; }
}

// ------------------- fused softmax + gather, layer 1 -------------------
__device__ __forceinline__ float lrelu(float v) { return v > 0.f ? v : 0.2f * v; }

__global__ void k_agg1() {
    int gw = (blockIdx.x * blockDim.x + threadIdx.x) >> 5;
    int lane = threadIdx.x & 31;
    if (gw >= NN) return;
    int beg = g_off[gw], end = g_off[gw + 1];
    float4 adv = *(const float4*)(g_ad1 + gw * 4);

    float4 mx = make_float4(-INFINITY, -INFINITY, -INFINITY, -INFINITY);
    for (int i = beg + lane; i < end; i += 32) {
        int s = g_csr[i];
        float4 a = *(const float4*)(g_as1 + s * 4);
        mx.x = fmaxf(mx.x, lrelu(a.x + adv.x));
        mx.y = fmaxf(mx.y, lrelu(a.y + adv.y));
        mx.z = fmaxf(mx.z, lrelu(a.z + adv.z));
        mx.w = fmaxf(mx.w, lrelu(a.w + adv.w));
    }
    #pragma unroll
    for (int o = 16; o; o >>= 1) {
        mx.x = fmaxf(mx.x, __shfl_xor_sync(0xffffffffu, mx.x, o));
        mx.y = fmaxf(mx.y, __shfl_xor_sync(0xffffffffu, mx.y, o));
        mx.z = fmaxf(mx.z, __shfl_xor_sync(0xffffffffu, mx.z, o));
        mx.w = fmaxf(mx.w, __shfl_xor_sync(0xffffffffu, mx.w, o));
    }
    float4 den = make_float4(0.f, 0.f, 0.f, 0.f);
    for (int i = beg + lane; i < end; i += 32) {
        int s = g_csr[i];
        float4 a = *(const float4*)(g_as1 + s * 4);
        den.x += expf(lrelu(a.x + adv.x) - mx.x);
        den.y += expf(lrelu(a.y + adv.y) - mx.y);
        den.z += expf(lrelu(a.z + adv.z) - mx.z);
        den.w += expf(lrelu(a.w + adv.w) - mx.w);
    }
    #pragma unroll
    for (int o = 16; o; o >>= 1) {
        den.x += __shfl_xor_sync(0xffffffffu, den.x, o);
        den.y += __shfl_xor_sync(0xffffffffu, den.y, o);
        den.z += __shfl_xor_sync(0xffffffffu, den.z, o);
        den.w += __shfl_xor_sync(0xffffffffu, den.w, o);
    }

    int hsel = lane >> 3;
    float ad_l  = hsel == 0 ? adv.x : hsel == 1 ? adv.y : hsel == 2 ? adv.z : adv.w;
    float m_l   = hsel == 0 ? mx.x  : hsel == 1 ? mx.y  : hsel == 2 ? mx.z  : mx.w;
    float den_l = hsel == 0 ? den.x : hsel == 1 ? den.y : hsel == 2 ? den.z : den.w;
    float inv_l = 1.f / (den_l + 1e-16f);

    float4 acc0 = make_float4(0.f, 0.f, 0.f, 0.f);
    float4 acc1 = make_float4(0.f, 0.f, 0.f, 0.f);
    const float4* __restrict__ h1v = (const float4*)g_h1;
    for (int i = beg; i < end; i++) {
        int s = g_csr[i];
        float a = g_as1[(s << 2) + hsel];
        float c = expf(lrelu(a + ad_l) - m_l) * inv_l;
        float4 v0 = h1v[(size_t)s * 64 + lane * 2];
        float4 v1 = h1v[(size_t)s * 64 + lane * 2 + 1];
        acc0.x += v0.x * c; acc0.y += v0.y * c; acc0.z += v0.z * c; acc0.w += v0.w * c;
        acc1.x += v1.x * c; acc1.y += v1.y * c; acc1.z += v1.z * c; acc1.w += v1.w * c;
    }
    float4* ov = (float4*)(g_out1 + (size_t)gw * HID);
    ov[lane * 2] = acc0;
    ov[lane * 2 + 1] = acc1;
}

// ------------------- fused softmax + gather, layer 2 -------------------
__global__ void k_agg2() {
    int gw = (blockIdx.x * blockDim.x + threadIdx.x) >> 5;
    int lane = threadIdx.x & 31;
    if (gw >= NN) return;
    int beg = g_off[gw], end = g_off[gw + 1];
    float ad = g_ad2[gw];

    float mx = -INFINITY;
    for (int i = beg + lane; i < end; i += 32)
        mx = fmaxf(mx, lrelu(g_as2[g_csr[i]] + ad));
    #pragma unroll
    for (int o = 16; o; o >>= 1) mx = fmaxf(mx, __shfl_xor_sync(0xffffffffu, mx, o));

    float den = 0.f;
    for (int i = beg + lane; i < end; i += 32)
        den += expf(lrelu(g_as2[g_csr[i]] + ad) - mx);
    #pragma unroll
    for (int o = 16; o; o >>= 1) den += __shfl_xor_sync(0xffffffffu, den, o);
    float inv = 1.f / (den + 1e-16f);

    float4 acc = make_float4(0.f, 0.f, 0.f, 0.f);
    const float4* __restrict__ h2v = (const float4*)g_h2;
    for (int i = beg; i < end; i++) {
        int s = g_csr[i];
        float c = expf(lrelu(g_as2[s] + ad) - mx) * inv;
        float4 v = h2v[(size_t)s * 32 + lane];
        acc.x += v.x * c; acc.y += v.y * c; acc.z += v.z * c; acc.w += v.w * c;
    }
    ((float4*)(g_out2 + (size_t)gw * OUT_DIM))[lane] = acc;
}

// ------------------- batchnorm -------------------
__global__ void k_zero_bn() {
    int i = threadIdx.x;
    if (i < HID) { g_sum[i] = 0.f; g_sqs[i] = 0.f; }
}
__global__ void k_stats1() {
    int c = threadIdx.x;
    int r0 = blockIdx.x * 256;
    int rend = r0 + 256; if (rend > NN) rend = NN;
    float s = 0.f, s2 = 0.f;
    for (int r = r0; r < rend; r++) {
        float v = g_out1[(size_t)r * HID + c];
        s += v; s2 += v * v;
    }
    atomicAdd(&g_sum[c], s); atomicAdd(&g_sqs[c], s2);
}
__global__ void k_apply1(const float* __restrict__ gamma, const float* __restrict__ beta) {
    int i = blockIdx.x * blockDim.x + threadIdx.x;
    if (i >= NN * HID) return;
    int c = i & (HID - 1);
    float mean = g_sum[c] * (1.f / NN);
    float var = g_sqs[c] * (1.f / NN) - mean * mean;
    float v = (g_out1[i] - mean) * rsqrtf(var + 1e-5f) * gamma[c] + beta[c];
    g_out1[i] = v > 0.f ? v : expm1f(v);   // ELU
}
__global__ void k_stats2() {
    int c = threadIdx.x;
    int r0 = blockIdx.x * 256;
    int rend = r0 + 256; if (rend > NN) rend = NN;
    float s = 0.f, s2 = 0.f;
    for (int r = r0; r < rend; r++) {
        float v = g_out2[(size_t)r * OUT_DIM + c];
        s += v; s2 += v * v;
    }
    atomicAdd(&g_sum[c], s); atomicAdd(&g_sqs[c], s2);
}
__global__ void k_apply2(const float* __restrict__ gamma, const float* __restrict__ beta,
                         float* __restrict__ out) {
    int i = blockIdx.x * blockDim.x + threadIdx.x;
    if (i >= NN * OUT_DIM) return;
    int c = i & (OUT_DIM - 1);
    float mean = g_sum[c] * (1.f / NN);
    float var = g_sqs[c] * (1.f / NN) - mean * mean;
    out[i] = (g_out2[i] - mean) * rsqrtf(var + 1e-5f) * gamma[c] + beta[c];
}

// ------------------- launch -------------------
extern "C" void kernel_launch(void* const* d_in, const int* in_sizes, int n_in,
                              void* d_out, int out_size) {
    const float* x     = (const float*)d_in[0];
    const void*  ei    = d_in[1];
    const float* W1    = (const float*)d_in[2];
    const float* asrc1 = (const float*)d_in[3];
    const float* adst1 = (const float*)d_in[4];
    const float* g1    = (const float*)d_in[6];
    const float* b1    = (const float*)d_in[7];
    const float* W2    = (const float*)d_in[8];
    const float* asrc2 = (const float*)d_in[9];
    const float* adst2 = (const float*)d_in[10];
    const float* g2    = (const float*)d_in[12];
    const float* b2    = (const float*)d_in[13];
    float* out = (float*)d_out;

    const int T = 256;
    const int EB = (ETOT + T - 1) / T;

    // CSR build
    k_detect<<<1, 1>>>(ei);
    k_decode<<<EB, T>>>(ei);
    k_count<<<EB, T>>>();
    k_scan<<<1, 1024>>>();
    k_fill<<<EB, T>>>();

    // layer 1
    k_gemm1<<<dim3(HID / 64, (NN + 127) / 128), 256>>>(x, W1);
    k_alpha1<<<(NN * 32 + T - 1) / T, T>>>(asrc1, adst1);
    k_agg1<<<(NN * 32 + T - 1) / T, T>>>();
    k_zero_bn<<<1, 256>>>();
    k_stats1<<<(NN + 255) / 256, 256>>>();
    k_apply1<<<(NN * HID + T - 1) / T, T>>>(g1, b1);

    // layer 2
    k_gemm2<<<dim3(OUT_DIM / 64, (NN + 127) / 128), 256>>>(W2);
    k_alpha2<<<(NN * 32 + T - 1) / T, T>>>(asrc2, adst2);
    k_agg2<<<(NN * 32 + T - 1) / T, T>>>();
    k_zero_bn<<<1, 256>>>();
    k_stats2<<<(NN + 255) / 256, 128>>>();
    k_apply2<<<(NN * OUT_DIM + T - 1) / T, T>>>(g2, b2, out);
}